// round 1
// baseline (speedup 1.0000x reference)
#include <cuda_runtime.h>
#include <cstdint>

// Problem constants (shapes fixed by the dataset)
#define N_NODES 100000
#define N_EDGES 3200000
#define IN_CH   512
#define HID     16
#define OUT_CH  2

// Scratch (device globals; no allocation allowed)
__device__ float g_y[N_NODES * 2];      // y = x @ (W1 W2)  [N, 2]
__device__ int   g_deg[N_NODES];        // edge-degree counts (excl. self loop)
__device__ float g_dinv[N_NODES];       // 1/sqrt(deg+1)
__device__ float g_w0[IN_CH];           // column 0 of W12
__device__ float g_w1[IN_CH];           // column 1 of W12
__device__ float g_c[2];                // b1 @ W2 + b2

// ---------------------------------------------------------------------------
// 1) zero output accumulator + degree counters
__global__ void init_kernel(float* __restrict__ out, int n_out, int n_nodes) {
    int i = blockIdx.x * blockDim.x + threadIdx.x;
    if (i < n_out) out[i] = 0.0f;
    if (i < n_nodes) g_deg[i] = 0;
}

// ---------------------------------------------------------------------------
// 2) fold W12 = W1 @ W2  (512x16 @ 16x2), and c = b1 @ W2 + b2
__global__ void w12_kernel(const float* __restrict__ W1,
                           const float* __restrict__ b1,
                           const float* __restrict__ W2,
                           const float* __restrict__ b2) {
    int t = threadIdx.x;           // 1024 threads: t = 2*i + k
    int i = t >> 1;
    int k = t & 1;
    float s = 0.0f;
#pragma unroll
    for (int h = 0; h < HID; h++) s += W1[i * HID + h] * W2[h * OUT_CH + k];
    if (k == 0) g_w0[i] = s; else g_w1[i] = s;
    if (t < 2) {
        float c = b2[t];
#pragma unroll
        for (int h = 0; h < HID; h++) c += b1[h] * W2[h * OUT_CH + t];
        g_c[t] = c;
    }
}

// ---------------------------------------------------------------------------
// 3) degree of targets (col)
__global__ void deg_kernel(const int* __restrict__ col, int n_edges) {
    int e = blockIdx.x * blockDim.x + threadIdx.x;
    if (e < n_edges) atomicAdd(&g_deg[col[e]], 1);
}

// 4) dinv = rsqrt(deg + 1)   (+1 = self loop; always > 0)
__global__ void dinv_kernel(int n_nodes) {
    int i = blockIdx.x * blockDim.x + threadIdx.x;
    if (i < n_nodes) g_dinv[i] = rsqrtf((float)(g_deg[i] + 1));
}

// ---------------------------------------------------------------------------
// 5) y = x @ W12   — warp per row, float4 coalesced, weights in registers
__global__ void gemm_kernel(const float* __restrict__ x, int n_nodes) {
    const int lane    = threadIdx.x & 31;
    const int warp    = (blockIdx.x * blockDim.x + threadIdx.x) >> 5;
    const int n_warps = (gridDim.x * blockDim.x) >> 5;

    // Preload this lane's weight slices (identical for every row it handles):
    // lane covers input channels {4*(lane+32j) .. +3} for j = 0..3
    float4 wa[4], wb[4];
#pragma unroll
    for (int j = 0; j < 4; j++) {
        int idx = lane + 32 * j;
        wa[j] = reinterpret_cast<const float4*>(g_w0)[idx];
        wb[j] = reinterpret_cast<const float4*>(g_w1)[idx];
    }

    for (int row = warp; row < n_nodes; row += n_warps) {
        const float4* xr = reinterpret_cast<const float4*>(x + (size_t)row * IN_CH);
        float s0 = 0.0f, s1 = 0.0f;
#pragma unroll
        for (int j = 0; j < 4; j++) {
            float4 v = __ldg(&xr[lane + 32 * j]);
            s0 += v.x * wa[j].x + v.y * wa[j].y + v.z * wa[j].z + v.w * wa[j].w;
            s1 += v.x * wb[j].x + v.y * wb[j].y + v.z * wb[j].z + v.w * wb[j].w;
        }
#pragma unroll
        for (int off = 16; off > 0; off >>= 1) {
            s0 += __shfl_down_sync(0xFFFFFFFFu, s0, off);
            s1 += __shfl_down_sync(0xFFFFFFFFu, s1, off);
        }
        if (lane == 0) {
            reinterpret_cast<float2*>(g_y)[row] = make_float2(s0, s1);
        }
    }
}

// ---------------------------------------------------------------------------
// 6) edge scatter: out[c] += y[r] * dinv[r] * dinv[c]   (vector red, 8B)
__global__ void scatter_kernel(const int* __restrict__ row,
                               const int* __restrict__ col,
                               float* __restrict__ out, int n_edges) {
    int e = blockIdx.x * blockDim.x + threadIdx.x;
    if (e >= n_edges) return;
    int r = __ldg(&row[e]);
    int c = __ldg(&col[e]);
    float w = g_dinv[r] * g_dinv[c];
    float2 yv = reinterpret_cast<const float2*>(g_y)[r];
    float a = yv.x * w;
    float b = yv.y * w;
    asm volatile("red.global.add.v2.f32 [%0], {%1, %2};"
                 :: "l"(out + (size_t)c * 2), "f"(a), "f"(b)
                 : "memory");
}

// ---------------------------------------------------------------------------
// 7) finalize: add self-loop term + bias constant
__global__ void finalize_kernel(float* __restrict__ out, int n_nodes) {
    int i = blockIdx.x * blockDim.x + threadIdx.x;
    if (i >= n_nodes) return;
    float di = g_dinv[i];
    float self_w = di * di;
    float2 a  = reinterpret_cast<float2*>(out)[i];
    float2 yv = reinterpret_cast<const float2*>(g_y)[i];
    a.x += yv.x * self_w + g_c[0];
    a.y += yv.y * self_w + g_c[1];
    reinterpret_cast<float2*>(out)[i] = a;
}

// ---------------------------------------------------------------------------
extern "C" void kernel_launch(void* const* d_in, const int* in_sizes, int n_in,
                              void* d_out, int out_size) {
    const float* x    = (const float*)d_in[0];
    const int*   ei   = (const int*)d_in[1];   // [2, E]
    const float* W1   = (const float*)d_in[2];
    const float* b1   = (const float*)d_in[3];
    const float* W2   = (const float*)d_in[4];
    const float* b2   = (const float*)d_in[5];
    float* out = (float*)d_out;

    const int n_edges = in_sizes[1] / 2;
    const int n_nodes = out_size / OUT_CH;
    const int* row = ei;             // source nodes
    const int* col = ei + n_edges;   // target nodes

    const int T = 256;

    init_kernel<<<(out_size + T - 1) / T, T>>>(out, out_size, n_nodes);
    w12_kernel<<<1, 1024>>>(W1, b1, W2, b2);
    deg_kernel<<<(n_edges + T - 1) / T, T>>>(col, n_edges);
    dinv_kernel<<<(n_nodes + T - 1) / T, T>>>(n_nodes);
    gemm_kernel<<<1024, T>>>(x, n_nodes);
    scatter_kernel<<<(n_edges + T - 1) / T, T>>>(row, col, out, n_edges);
    finalize_kernel<<<(n_nodes + T - 1) / T, T>>>(out, n_nodes);
}

// round 2
// speedup vs baseline: 1.1444x; 1.1444x over previous
#include <cuda_runtime.h>
#include <cstdint>

#define N_NODES 100000
#define N_EDGES 3200000
#define IN_CH   512
#define HID     16
#define OUT_CH  2

// Scratch (device globals; no allocation allowed)
__device__ float g_s[N_NODES * 2];      // s = (x @ W12) * dinv   [N, 2]
__device__ int   g_deg[N_NODES];        // edge-degree counts (excl. self loop)
__device__ float g_dinv[N_NODES];       // 1/sqrt(deg+1)
__device__ float g_w0[IN_CH];           // column 0 of W12 = W1@W2
__device__ float g_w1[IN_CH];           // column 1 of W12
__device__ float g_c[2];                // b1 @ W2 + b2

// ---------------------------------------------------------------------------
// K1: zero degree counters + fold weights/bias (block 0)
__global__ void prep_kernel(const float* __restrict__ W1,
                            const float* __restrict__ b1,
                            const float* __restrict__ W2,
                            const float* __restrict__ b2,
                            int n_nodes) {
    int stride = gridDim.x * blockDim.x;
    for (int i = blockIdx.x * blockDim.x + threadIdx.x; i < n_nodes; i += stride)
        g_deg[i] = 0;

    if (blockIdx.x == 0) {
        int t = threadIdx.x;                 // 512 threads
        if (t < IN_CH) {
            float s0 = 0.0f, s1 = 0.0f;
#pragma unroll
            for (int h = 0; h < HID; h++) {
                float w = W1[t * HID + h];
                s0 += w * W2[h * OUT_CH + 0];
                s1 += w * W2[h * OUT_CH + 1];
            }
            g_w0[t] = s0;
            g_w1[t] = s1;
        }
        if (t < OUT_CH) {
            float c = b2[t];
#pragma unroll
            for (int h = 0; h < HID; h++) c += b1[h] * W2[h * OUT_CH + t];
            g_c[t] = c;
        }
    }
}

// ---------------------------------------------------------------------------
// K2: degree of targets, 4 edges per thread (int4 loads)
__global__ void deg_kernel(const int* __restrict__ col, int n_edges) {
    int t = blockIdx.x * blockDim.x + threadIdx.x;
    int e = t * 4;
    if (e + 3 < n_edges) {
        int4 c = *reinterpret_cast<const int4*>(col + e);
        atomicAdd(&g_deg[c.x], 1);
        atomicAdd(&g_deg[c.y], 1);
        atomicAdd(&g_deg[c.z], 1);
        atomicAdd(&g_deg[c.w], 1);
    } else {
        for (; e < n_edges; e++) atomicAdd(&g_deg[col[e]], 1);
    }
}

// ---------------------------------------------------------------------------
// K3: fused  dinv + GEMM + self-loop/bias init of out
//   per row: di = rsqrt(deg+1); y = x[row] @ W12;
//            s = y*di  (stored for scatter);  out[row] = s*di + c
__global__ void gemm_kernel(const float* __restrict__ x,
                            float* __restrict__ out, int n_nodes) {
    const int lane    = threadIdx.x & 31;
    const int warp    = (blockIdx.x * blockDim.x + threadIdx.x) >> 5;
    const int n_warps = (gridDim.x * blockDim.x) >> 5;

    // Per-lane weight slices: channels {4*(lane+32j)..+3}, j=0..3
    float4 wa[4], wb[4];
#pragma unroll
    for (int j = 0; j < 4; j++) {
        int idx = lane + 32 * j;
        wa[j] = reinterpret_cast<const float4*>(g_w0)[idx];
        wb[j] = reinterpret_cast<const float4*>(g_w1)[idx];
    }
    const float c0 = g_c[0], c1 = g_c[1];

    for (int row = warp; row < n_nodes; row += n_warps) {
        const float4* xr = reinterpret_cast<const float4*>(x + (size_t)row * IN_CH);
        float s0 = 0.0f, s1 = 0.0f;
#pragma unroll
        for (int j = 0; j < 4; j++) {
            float4 v = __ldg(&xr[lane + 32 * j]);
            s0 += v.x * wa[j].x + v.y * wa[j].y + v.z * wa[j].z + v.w * wa[j].w;
            s1 += v.x * wb[j].x + v.y * wb[j].y + v.z * wb[j].z + v.w * wb[j].w;
        }
#pragma unroll
        for (int off = 16; off > 0; off >>= 1) {
            s0 += __shfl_down_sync(0xFFFFFFFFu, s0, off);
            s1 += __shfl_down_sync(0xFFFFFFFFu, s1, off);
        }
        if (lane == 0) {
            float di = rsqrtf((float)(g_deg[row] + 1));
            g_dinv[row] = di;
            float a0 = s0 * di, a1 = s1 * di;            // s = y*dinv
            reinterpret_cast<float2*>(g_s)[row] = make_float2(a0, a1);
            // self-loop term + bias: y*dinv^2 + c = s*dinv + c
            reinterpret_cast<float2*>(out)[row] = make_float2(a0 * di + c0,
                                                              a1 * di + c1);
        }
    }
}

// ---------------------------------------------------------------------------
// K4: edge scatter  out[c] += s[r] * dinv[c]   (4 edges/thread, 8B red each)
__global__ void scatter_kernel(const int* __restrict__ row,
                               const int* __restrict__ col,
                               float* __restrict__ out, int n_edges) {
    int t = blockIdx.x * blockDim.x + threadIdx.x;
    int e = t * 4;
    if (e + 3 < n_edges) {
        int4 r = *reinterpret_cast<const int4*>(row + e);
        int4 c = *reinterpret_cast<const int4*>(col + e);

        float2 sx = reinterpret_cast<const float2*>(g_s)[r.x];
        float2 sy = reinterpret_cast<const float2*>(g_s)[r.y];
        float2 sz = reinterpret_cast<const float2*>(g_s)[r.z];
        float2 sw = reinterpret_cast<const float2*>(g_s)[r.w];
        float dx = g_dinv[c.x], dy = g_dinv[c.y];
        float dz = g_dinv[c.z], dw = g_dinv[c.w];

        asm volatile("red.global.add.v2.f32 [%0], {%1, %2};"
                     :: "l"(out + (size_t)c.x * 2), "f"(sx.x * dx), "f"(sx.y * dx) : "memory");
        asm volatile("red.global.add.v2.f32 [%0], {%1, %2};"
                     :: "l"(out + (size_t)c.y * 2), "f"(sy.x * dy), "f"(sy.y * dy) : "memory");
        asm volatile("red.global.add.v2.f32 [%0], {%1, %2};"
                     :: "l"(out + (size_t)c.z * 2), "f"(sz.x * dz), "f"(sz.y * dz) : "memory");
        asm volatile("red.global.add.v2.f32 [%0], {%1, %2};"
                     :: "l"(out + (size_t)c.w * 2), "f"(sw.x * dw), "f"(sw.y * dw) : "memory");
    } else {
        for (; e < n_edges; e++) {
            int r1 = row[e], c1 = col[e];
            float2 sv = reinterpret_cast<const float2*>(g_s)[r1];
            float d = g_dinv[c1];
            asm volatile("red.global.add.v2.f32 [%0], {%1, %2};"
                         :: "l"(out + (size_t)c1 * 2), "f"(sv.x * d), "f"(sv.y * d) : "memory");
        }
    }
}

// ---------------------------------------------------------------------------
extern "C" void kernel_launch(void* const* d_in, const int* in_sizes, int n_in,
                              void* d_out, int out_size) {
    const float* x  = (const float*)d_in[0];
    const int*   ei = (const int*)d_in[1];   // [2, E]
    const float* W1 = (const float*)d_in[2];
    const float* b1 = (const float*)d_in[3];
    const float* W2 = (const float*)d_in[4];
    const float* b2 = (const float*)d_in[5];
    float* out = (float*)d_out;

    const int n_edges = in_sizes[1] / 2;
    const int n_nodes = out_size / OUT_CH;
    const int* row = ei;             // source nodes
    const int* col = ei + n_edges;   // target nodes

    const int T = 256;
    const int edge_threads = (n_edges + 3) / 4;

    prep_kernel<<<128, 512>>>(W1, b1, W2, b2, n_nodes);
    deg_kernel<<<(edge_threads + T - 1) / T, T>>>(col, n_edges);
    gemm_kernel<<<1024, T>>>(x, out, n_nodes);
    scatter_kernel<<<(edge_threads + T - 1) / T, T>>>(row, col, out, n_edges);
}

// round 3
// speedup vs baseline: 1.2511x; 1.0932x over previous
#include <cuda_runtime.h>
#include <cstdint>

#define N_NODES 100000
#define N_EDGES 3200000
#define IN_CH   512
#define HID     16
#define OUT_CH  2

// Scratch (device globals; no allocation allowed)
__device__ float g_s[N_NODES * 2];      // y = x@W12, then s = y*dinv  [N, 2]
__device__ int   g_deg[N_NODES];        // edge-degree counts (excl. self loop)
__device__ float g_dinv[N_NODES];       // 1/sqrt(deg+1)
__device__ float g_w0[IN_CH];           // column 0 of W12 = W1@W2
__device__ float g_w1[IN_CH];           // column 1 of W12
__device__ float g_c[2];                // b1 @ W2 + b2

// ---------------------------------------------------------------------------
// K1: zero degree counters + fold weights/bias (block 0)
__global__ void prep_kernel(const float* __restrict__ W1,
                            const float* __restrict__ b1,
                            const float* __restrict__ W2,
                            const float* __restrict__ b2,
                            int n_nodes) {
    int stride = gridDim.x * blockDim.x;
    for (int i = blockIdx.x * blockDim.x + threadIdx.x; i < n_nodes; i += stride)
        g_deg[i] = 0;

    if (blockIdx.x == 0) {
        int t = threadIdx.x;                 // 512 threads
        if (t < IN_CH) {
            float s0 = 0.0f, s1 = 0.0f;
#pragma unroll
            for (int h = 0; h < HID; h++) {
                float w = W1[t * HID + h];
                s0 += w * W2[h * OUT_CH + 0];
                s1 += w * W2[h * OUT_CH + 1];
            }
            g_w0[t] = s0;
            g_w1[t] = s1;
        }
        if (t < OUT_CH) {
            float c = b2[t];
#pragma unroll
            for (int h = 0; h < HID; h++) c += b1[h] * W2[h * OUT_CH + t];
            g_c[t] = c;
        }
    }
}

// ---------------------------------------------------------------------------
// K2: fused  deg (L2-atomic bound)  ||  y = x @ W12 (DRAM bound)
//   blocks [0, DEG_BLOCKS): degree atomics over edges (grid-stride, int4)
//   blocks [DEG_BLOCKS, ...): warp-per-row GEMM storing raw y into g_s
#define DEG_BLOCKS 232
__global__ void fused_kernel(const float* __restrict__ x,
                             const int* __restrict__ col,
                             int n_edges, int n_nodes) {
    if (blockIdx.x < DEG_BLOCKS) {
        // ---- degree part ----
        int n4 = n_edges >> 2;  // number of full int4 chunks
        int stride = DEG_BLOCKS * blockDim.x;
        for (int t = blockIdx.x * blockDim.x + threadIdx.x; t < n4; t += stride) {
            int4 c = __ldg(reinterpret_cast<const int4*>(col) + t);
            atomicAdd(&g_deg[c.x], 1);
            atomicAdd(&g_deg[c.y], 1);
            atomicAdd(&g_deg[c.z], 1);
            atomicAdd(&g_deg[c.w], 1);
        }
        // tail
        if (blockIdx.x == 0 && threadIdx.x < (n_edges & 3)) {
            atomicAdd(&g_deg[col[(n4 << 2) + threadIdx.x]], 1);
        }
        return;
    }

    // ---- GEMM part: warp per row, float4 coalesced ----
    const int lane    = threadIdx.x & 31;
    const int gwarp   = (((blockIdx.x - DEG_BLOCKS) * blockDim.x) + threadIdx.x) >> 5;
    const int n_warps = ((gridDim.x - DEG_BLOCKS) * blockDim.x) >> 5;

    float4 wa[4], wb[4];
#pragma unroll
    for (int j = 0; j < 4; j++) {
        int idx = lane + 32 * j;
        wa[j] = reinterpret_cast<const float4*>(g_w0)[idx];
        wb[j] = reinterpret_cast<const float4*>(g_w1)[idx];
    }

    for (int row = gwarp; row < n_nodes; row += n_warps) {
        const float4* xr = reinterpret_cast<const float4*>(x + (size_t)row * IN_CH);
        float s0 = 0.0f, s1 = 0.0f;
#pragma unroll
        for (int j = 0; j < 4; j++) {
            float4 v = __ldg(&xr[lane + 32 * j]);
            s0 += v.x * wa[j].x + v.y * wa[j].y + v.z * wa[j].z + v.w * wa[j].w;
            s1 += v.x * wb[j].x + v.y * wb[j].y + v.z * wb[j].z + v.w * wb[j].w;
        }
#pragma unroll
        for (int off = 16; off > 0; off >>= 1) {
            s0 += __shfl_down_sync(0xFFFFFFFFu, s0, off);
            s1 += __shfl_down_sync(0xFFFFFFFFu, s1, off);
        }
        if (lane == 0) {
            reinterpret_cast<float2*>(g_s)[row] = make_float2(s0, s1);  // raw y
        }
    }
}

// ---------------------------------------------------------------------------
// K3: node prep:  dinv = rsqrt(deg+1);  s = y*dinv;  out = s  (self-loop seed)
__global__ void nodeprep_kernel(float* __restrict__ out, int n_nodes) {
    int i = blockIdx.x * blockDim.x + threadIdx.x;
    if (i >= n_nodes) return;
    float di = rsqrtf((float)(g_deg[i] + 1));
    g_dinv[i] = di;
    float2 y = reinterpret_cast<const float2*>(g_s)[i];
    float2 s = make_float2(y.x * di, y.y * di);
    reinterpret_cast<float2*>(g_s)[i] = s;
    reinterpret_cast<float2*>(out)[i] = s;   // accumulator seeded with s[c]
}

// ---------------------------------------------------------------------------
// K4: edge scatter  out[c] += s[r]   (UNscaled — one 8B read + one 8B red/edge)
__global__ void scatter_kernel(const int* __restrict__ row,
                               const int* __restrict__ col,
                               float* __restrict__ out, int n_edges) {
    int t = blockIdx.x * blockDim.x + threadIdx.x;
    int e = t * 4;
    if (e + 3 < n_edges) {
        int4 r = *reinterpret_cast<const int4*>(row + e);
        int4 c = *reinterpret_cast<const int4*>(col + e);

        float2 sx = __ldg(reinterpret_cast<const float2*>(g_s) + r.x);
        float2 sy = __ldg(reinterpret_cast<const float2*>(g_s) + r.y);
        float2 sz = __ldg(reinterpret_cast<const float2*>(g_s) + r.z);
        float2 sw = __ldg(reinterpret_cast<const float2*>(g_s) + r.w);

        asm volatile("red.global.add.v2.f32 [%0], {%1, %2};"
                     :: "l"(out + (size_t)c.x * 2), "f"(sx.x), "f"(sx.y) : "memory");
        asm volatile("red.global.add.v2.f32 [%0], {%1, %2};"
                     :: "l"(out + (size_t)c.y * 2), "f"(sy.x), "f"(sy.y) : "memory");
        asm volatile("red.global.add.v2.f32 [%0], {%1, %2};"
                     :: "l"(out + (size_t)c.z * 2), "f"(sz.x), "f"(sz.y) : "memory");
        asm volatile("red.global.add.v2.f32 [%0], {%1, %2};"
                     :: "l"(out + (size_t)c.w * 2), "f"(sw.x), "f"(sw.y) : "memory");
    } else {
        for (; e < n_edges; e++) {
            int r1 = row[e], c1 = col[e];
            float2 sv = __ldg(reinterpret_cast<const float2*>(g_s) + r1);
            asm volatile("red.global.add.v2.f32 [%0], {%1, %2};"
                         :: "l"(out + (size_t)c1 * 2), "f"(sv.x), "f"(sv.y) : "memory");
        }
    }
}

// ---------------------------------------------------------------------------
// K5: finalize:  out[i] = out[i]*dinv[i] + c
__global__ void finalize_kernel(float* __restrict__ out, int n_nodes) {
    int i = blockIdx.x * blockDim.x + threadIdx.x;
    if (i >= n_nodes) return;
    float di = g_dinv[i];
    float2 a = reinterpret_cast<float2*>(out)[i];
    a.x = a.x * di + g_c[0];
    a.y = a.y * di + g_c[1];
    reinterpret_cast<float2*>(out)[i] = a;
}

// ---------------------------------------------------------------------------
extern "C" void kernel_launch(void* const* d_in, const int* in_sizes, int n_in,
                              void* d_out, int out_size) {
    const float* x  = (const float*)d_in[0];
    const int*   ei = (const int*)d_in[1];   // [2, E]
    const float* W1 = (const float*)d_in[2];
    const float* b1 = (const float*)d_in[3];
    const float* W2 = (const float*)d_in[4];
    const float* b2 = (const float*)d_in[5];
    float* out = (float*)d_out;

    const int n_edges = in_sizes[1] / 2;
    const int n_nodes = out_size / OUT_CH;
    const int* row = ei;             // source nodes
    const int* col = ei + n_edges;   // target nodes

    const int T = 256;
    const int edge_threads = (n_edges + 3) / 4;

    prep_kernel<<<128, 512>>>(W1, b1, W2, b2, n_nodes);
    fused_kernel<<<DEG_BLOCKS + 1792, T>>>(x, col, n_edges, n_nodes);
    nodeprep_kernel<<<(n_nodes + T - 1) / T, T>>>(out, n_nodes);
    scatter_kernel<<<(edge_threads + T - 1) / T, T>>>(row, col, out, n_edges);
    finalize_kernel<<<(n_nodes + T - 1) / T, T>>>(out, n_nodes);
}

// round 4
// speedup vs baseline: 1.3103x; 1.0473x over previous
#include <cuda_runtime.h>
#include <cstdint>

#define N_NODES 100000
#define N_EDGES 3200000
#define IN_CH   512
#define HID     16
#define OUT_CH  2

// Scratch (device globals; no allocation allowed)
__device__ __align__(16) float g_s[N_NODES * 2];   // y = x@W12, then s = y*dinv
__device__ __align__(16) int   g_deg[N_NODES];     // zero-init; re-zeroed by finalize
__device__ __align__(16) float g_dinv[N_NODES];    // 1/sqrt(deg+1)
__device__ __align__(16) float g_w0[IN_CH];        // col 0 of W12 = W1@W2
__device__ __align__(16) float g_w1[IN_CH];        // col 1 of W12
__device__ float g_c[2];                           // b1@W2 + b2

// ---------------------------------------------------------------------------
// K1: fold weights/bias (single block, 512 threads)
__global__ void prep_kernel(const float* __restrict__ W1,
                            const float* __restrict__ b1,
                            const float* __restrict__ W2,
                            const float* __restrict__ b2) {
    int t = threadIdx.x;                 // 512 threads == IN_CH
    float s0 = 0.0f, s1 = 0.0f;
#pragma unroll
    for (int h = 0; h < HID; h++) {
        float w = W1[t * HID + h];
        s0 += w * W2[h * OUT_CH + 0];
        s1 += w * W2[h * OUT_CH + 1];
    }
    g_w0[t] = s0;
    g_w1[t] = s1;
    if (t < OUT_CH) {
        float c = b2[t];
#pragma unroll
        for (int h = 0; h < HID; h++) c += b1[h] * W2[h * OUT_CH + t];
        g_c[t] = c;
    }
}

// ---------------------------------------------------------------------------
// K2: fused  deg (L2-atomic bound)  ||  y = x @ W12 (DRAM bound)
//   blocks [0, DEG_BLOCKS): degree atomics over edges (grid-stride, int4)
//   remaining blocks: warp computes 4 rows, 16 loads in flight
#define DEG_BLOCKS 160
__global__ void __launch_bounds__(256, 2)
fused_kernel(const float* __restrict__ x,
             const int* __restrict__ col,
             int n_edges, int n_nodes) {
    if (blockIdx.x < DEG_BLOCKS) {
        int n4 = n_edges >> 2;
        int stride = DEG_BLOCKS * blockDim.x;
        for (int t = blockIdx.x * blockDim.x + threadIdx.x; t < n4; t += stride) {
            int4 c = __ldg(reinterpret_cast<const int4*>(col) + t);
            atomicAdd(&g_deg[c.x], 1);
            atomicAdd(&g_deg[c.y], 1);
            atomicAdd(&g_deg[c.z], 1);
            atomicAdd(&g_deg[c.w], 1);
        }
        if (blockIdx.x == 0 && threadIdx.x < (n_edges & 3)) {
            atomicAdd(&g_deg[col[(n4 << 2) + threadIdx.x]], 1);
        }
        return;
    }

    // ---- GEMM part: warp computes 4 consecutive rows ----
    const int lane  = threadIdx.x & 31;
    const int gwarp = (((blockIdx.x - DEG_BLOCKS) * blockDim.x) + threadIdx.x) >> 5;
    const int rbase = gwarp * 4;
    if (rbase >= n_nodes) return;

    // Per-lane weight slices: channels {4*(lane+32j)..+3}, j=0..3
    float4 wa[4], wb[4];
#pragma unroll
    for (int j = 0; j < 4; j++) {
        int idx = lane + 32 * j;
        wa[j] = reinterpret_cast<const float4*>(g_w0)[idx];
        wb[j] = reinterpret_cast<const float4*>(g_w1)[idx];
    }

    const float4* x4 = reinterpret_cast<const float4*>(x);

    if (rbase + 4 <= n_nodes) {
        // Issue all 16 loads first (max MLP), then FMA, then one fused reduction
        float4 v[4][4];
#pragma unroll
        for (int r = 0; r < 4; r++) {
            const float4* xr = x4 + (size_t)(rbase + r) * (IN_CH / 4);
#pragma unroll
            for (int j = 0; j < 4; j++) v[r][j] = __ldg(xr + lane + 32 * j);
        }

        float s00 = 0.f, s01 = 0.f, s10 = 0.f, s11 = 0.f;
        float s20 = 0.f, s21 = 0.f, s30 = 0.f, s31 = 0.f;
#pragma unroll
        for (int j = 0; j < 4; j++) {
            s00 += v[0][j].x * wa[j].x + v[0][j].y * wa[j].y + v[0][j].z * wa[j].z + v[0][j].w * wa[j].w;
            s01 += v[0][j].x * wb[j].x + v[0][j].y * wb[j].y + v[0][j].z * wb[j].z + v[0][j].w * wb[j].w;
            s10 += v[1][j].x * wa[j].x + v[1][j].y * wa[j].y + v[1][j].z * wa[j].z + v[1][j].w * wa[j].w;
            s11 += v[1][j].x * wb[j].x + v[1][j].y * wb[j].y + v[1][j].z * wb[j].z + v[1][j].w * wb[j].w;
            s20 += v[2][j].x * wa[j].x + v[2][j].y * wa[j].y + v[2][j].z * wa[j].z + v[2][j].w * wa[j].w;
            s21 += v[2][j].x * wb[j].x + v[2][j].y * wb[j].y + v[2][j].z * wb[j].z + v[2][j].w * wb[j].w;
            s30 += v[3][j].x * wa[j].x + v[3][j].y * wa[j].y + v[3][j].z * wa[j].z + v[3][j].w * wa[j].w;
            s31 += v[3][j].x * wb[j].x + v[3][j].y * wb[j].y + v[3][j].z * wb[j].z + v[3][j].w * wb[j].w;
        }
        // Interleaved butterfly: 8 independent chains pipeline the shfl latency
#pragma unroll
        for (int off = 16; off > 0; off >>= 1) {
            s00 += __shfl_xor_sync(0xFFFFFFFFu, s00, off);
            s01 += __shfl_xor_sync(0xFFFFFFFFu, s01, off);
            s10 += __shfl_xor_sync(0xFFFFFFFFu, s10, off);
            s11 += __shfl_xor_sync(0xFFFFFFFFu, s11, off);
            s20 += __shfl_xor_sync(0xFFFFFFFFu, s20, off);
            s21 += __shfl_xor_sync(0xFFFFFFFFu, s21, off);
            s30 += __shfl_xor_sync(0xFFFFFFFFu, s30, off);
            s31 += __shfl_xor_sync(0xFFFFFFFFu, s31, off);
        }
        if (lane < 4) {
            float o0, o1;
            if      (lane == 0) { o0 = s00; o1 = s01; }
            else if (lane == 1) { o0 = s10; o1 = s11; }
            else if (lane == 2) { o0 = s20; o1 = s21; }
            else                { o0 = s30; o1 = s31; }
            reinterpret_cast<float2*>(g_s)[rbase + lane] = make_float2(o0, o1);
        }
    } else {
        // tail rows (not hit for N=100000, kept for generality)
        for (int row = rbase; row < n_nodes; row++) {
            const float4* xr = x4 + (size_t)row * (IN_CH / 4);
            float s0 = 0.f, s1 = 0.f;
#pragma unroll
            for (int j = 0; j < 4; j++) {
                float4 v0 = __ldg(xr + lane + 32 * j);
                s0 += v0.x * wa[j].x + v0.y * wa[j].y + v0.z * wa[j].z + v0.w * wa[j].w;
                s1 += v0.x * wb[j].x + v0.y * wb[j].y + v0.z * wb[j].z + v0.w * wb[j].w;
            }
#pragma unroll
            for (int off = 16; off > 0; off >>= 1) {
                s0 += __shfl_xor_sync(0xFFFFFFFFu, s0, off);
                s1 += __shfl_xor_sync(0xFFFFFFFFu, s1, off);
            }
            if (lane == 0)
                reinterpret_cast<float2*>(g_s)[row] = make_float2(s0, s1);
        }
    }
}

// ---------------------------------------------------------------------------
// K3: node prep (2 nodes/thread): dinv = rsqrt(deg+1); s = y*dinv; out = s
__global__ void nodeprep_kernel(float* __restrict__ out, int n_nodes) {
    int i = (blockIdx.x * blockDim.x + threadIdx.x) * 2;
    if (i + 1 < n_nodes) {
        float4 y = *reinterpret_cast<float4*>(g_s + i * 2);
        float d0 = rsqrtf((float)(g_deg[i] + 1));
        float d1 = rsqrtf((float)(g_deg[i + 1] + 1));
        y.x *= d0; y.y *= d0; y.z *= d1; y.w *= d1;
        *reinterpret_cast<float4*>(g_s + i * 2) = y;
        *reinterpret_cast<float4*>(out + i * 2) = y;   // accumulator seeded with s[c]
        *reinterpret_cast<float2*>(g_dinv + i) = make_float2(d0, d1);
    } else if (i < n_nodes) {
        float di = rsqrtf((float)(g_deg[i] + 1));
        g_dinv[i] = di;
        float2 y = reinterpret_cast<const float2*>(g_s)[i];
        float2 s = make_float2(y.x * di, y.y * di);
        reinterpret_cast<float2*>(g_s)[i] = s;
        reinterpret_cast<float2*>(out)[i] = s;
    }
}

// ---------------------------------------------------------------------------
// K4: edge scatter  out[c] += s[r]   (one 8B gather + one 8B v2-red per edge)
__global__ void scatter_kernel(const int* __restrict__ row,
                               const int* __restrict__ col,
                               float* __restrict__ out, int n_edges) {
    int t = blockIdx.x * blockDim.x + threadIdx.x;
    int e = t * 4;
    if (e + 3 < n_edges) {
        int4 r = *reinterpret_cast<const int4*>(row + e);
        int4 c = *reinterpret_cast<const int4*>(col + e);

        float2 sx = __ldg(reinterpret_cast<const float2*>(g_s) + r.x);
        float2 sy = __ldg(reinterpret_cast<const float2*>(g_s) + r.y);
        float2 sz = __ldg(reinterpret_cast<const float2*>(g_s) + r.z);
        float2 sw = __ldg(reinterpret_cast<const float2*>(g_s) + r.w);

        asm volatile("red.global.add.v2.f32 [%0], {%1, %2};"
                     :: "l"(out + (size_t)c.x * 2), "f"(sx.x), "f"(sx.y) : "memory");
        asm volatile("red.global.add.v2.f32 [%0], {%1, %2};"
                     :: "l"(out + (size_t)c.y * 2), "f"(sy.x), "f"(sy.y) : "memory");
        asm volatile("red.global.add.v2.f32 [%0], {%1, %2};"
                     :: "l"(out + (size_t)c.z * 2), "f"(sz.x), "f"(sz.y) : "memory");
        asm volatile("red.global.add.v2.f32 [%0], {%1, %2};"
                     :: "l"(out + (size_t)c.w * 2), "f"(sw.x), "f"(sw.y) : "memory");
    } else {
        for (; e < n_edges; e++) {
            int r1 = row[e], c1 = col[e];
            float2 sv = __ldg(reinterpret_cast<const float2*>(g_s) + r1);
            asm volatile("red.global.add.v2.f32 [%0], {%1, %2};"
                         :: "l"(out + (size_t)c1 * 2), "f"(sv.x), "f"(sv.y) : "memory");
        }
    }
}

// ---------------------------------------------------------------------------
// K5: finalize (2 nodes/thread): out = out*dinv + c; also re-zero g_deg
__global__ void finalize_kernel(float* __restrict__ out, int n_nodes) {
    int i = (blockIdx.x * blockDim.x + threadIdx.x) * 2;
    float c0 = g_c[0], c1 = g_c[1];
    if (i + 1 < n_nodes) {
        float4 a = *reinterpret_cast<float4*>(out + i * 2);
        float2 d = *reinterpret_cast<float2*>(g_dinv + i);
        a.x = a.x * d.x + c0;  a.y = a.y * d.x + c1;
        a.z = a.z * d.y + c0;  a.w = a.w * d.y + c1;
        *reinterpret_cast<float4*>(out + i * 2) = a;
        *reinterpret_cast<int2*>(g_deg + i) = make_int2(0, 0);  // ready for next run
    } else if (i < n_nodes) {
        float di = g_dinv[i];
        float2 a = reinterpret_cast<float2*>(out)[i];
        a.x = a.x * di + c0;
        a.y = a.y * di + c1;
        reinterpret_cast<float2*>(out)[i] = a;
        g_deg[i] = 0;
    }
}

// ---------------------------------------------------------------------------
extern "C" void kernel_launch(void* const* d_in, const int* in_sizes, int n_in,
                              void* d_out, int out_size) {
    const float* x  = (const float*)d_in[0];
    const int*   ei = (const int*)d_in[1];   // [2, E]
    const float* W1 = (const float*)d_in[2];
    const float* b1 = (const float*)d_in[3];
    const float* W2 = (const float*)d_in[4];
    const float* b2 = (const float*)d_in[5];
    float* out = (float*)d_out;

    const int n_edges = in_sizes[1] / 2;
    const int n_nodes = out_size / OUT_CH;
    const int* row = ei;             // source nodes
    const int* col = ei + n_edges;   // target nodes

    const int T = 256;
    const int edge_threads = (n_edges + 3) / 4;
    const int gemm_blocks = (n_nodes + 4 * (T / 32) - 1) / (4 * (T / 32));  // 4 rows/warp
    const int node2_blocks = ((n_nodes + 1) / 2 + T - 1) / T;

    prep_kernel<<<1, 512>>>(W1, b1, W2, b2);
    fused_kernel<<<DEG_BLOCKS + gemm_blocks, T>>>(x, col, n_edges, n_nodes);
    nodeprep_kernel<<<node2_blocks, T>>>(out, n_nodes);
    scatter_kernel<<<(edge_threads + T - 1) / T, T>>>(row, col, out, n_edges);
    finalize_kernel<<<node2_blocks, T>>>(out, n_nodes);
}